// round 1
// baseline (speedup 1.0000x reference)
#include <cuda_runtime.h>

// Problem constants
#define BB 2
#define SS 2048
#define DD 1024
#define HH 16
#define DK 64
#define MROWS (BB * SS)   // 4096

// Scratch (static device globals — allocation-guard safe)
__device__ float g_q[MROWS * DD];
__device__ float g_k[MROWS * DD];
__device__ float g_v[MROWS * DD];
__device__ float g_o[MROWS * DD];

// ---------------------------------------------------------------------------
// SGEMM: C[M,N] = A[M,K] @ W[N,K]^T + bias[N]
// 128x128 block tile, BK=8, 256 threads, 8x8 micro-tile (4+4 split layout)
// ---------------------------------------------------------------------------
__global__ __launch_bounds__(256) void sgemm_bias_kernel(
    const float* __restrict__ A, const float* __restrict__ W,
    const float* __restrict__ bias, float* __restrict__ C,
    int M, int N, int K)
{
    __shared__ float As[8][128];
    __shared__ float Bs[8][128];

    const int tid = threadIdx.x;
    const int tx = tid & 15;        // 0..15 -> n
    const int ty = tid >> 4;        // 0..15 -> m
    const int rowBase = blockIdx.y * 128;
    const int colBase = blockIdx.x * 128;

    // load mapping: one float4 per thread per tile for A and W
    const int lrow = tid >> 1;          // 0..127
    const int lkc  = (tid & 1) * 4;     // 0 or 4
    const float* Aptr = A + (size_t)(rowBase + lrow) * K + lkc;
    const float* Wptr = W + (size_t)(colBase + lrow) * K + lkc;

    float acc[8][8];
#pragma unroll
    for (int i = 0; i < 8; i++)
#pragma unroll
        for (int j = 0; j < 8; j++) acc[i][j] = 0.0f;

    for (int k0 = 0; k0 < K; k0 += 8) {
        float4 av = *(const float4*)(Aptr + k0);
        float4 wv = *(const float4*)(Wptr + k0);
        As[lkc + 0][lrow] = av.x;
        As[lkc + 1][lrow] = av.y;
        As[lkc + 2][lrow] = av.z;
        As[lkc + 3][lrow] = av.w;
        Bs[lkc + 0][lrow] = wv.x;
        Bs[lkc + 1][lrow] = wv.y;
        Bs[lkc + 2][lrow] = wv.z;
        Bs[lkc + 3][lrow] = wv.w;
        __syncthreads();

#pragma unroll
        for (int kk = 0; kk < 8; kk++) {
            float4 a0 = *(const float4*)&As[kk][ty * 4];
            float4 a1 = *(const float4*)&As[kk][64 + ty * 4];
            float4 b0 = *(const float4*)&Bs[kk][tx * 4];
            float4 b1 = *(const float4*)&Bs[kk][64 + tx * 4];
            float a[8] = {a0.x, a0.y, a0.z, a0.w, a1.x, a1.y, a1.z, a1.w};
            float b[8] = {b0.x, b0.y, b0.z, b0.w, b1.x, b1.y, b1.z, b1.w};
#pragma unroll
            for (int i = 0; i < 8; i++)
#pragma unroll
                for (int j = 0; j < 8; j++)
                    acc[i][j] = fmaf(a[i], b[j], acc[i][j]);
        }
        __syncthreads();
    }

    // epilogue with bias, vectorized stores
    float4 bia0 = *(const float4*)(bias + colBase + tx * 4);
    float4 bia1 = *(const float4*)(bias + colBase + 64 + tx * 4);
#pragma unroll
    for (int i = 0; i < 8; i++) {
        int m = rowBase + ((i < 4) ? (ty * 4 + i) : (64 + ty * 4 + i - 4));
        float4 o0, o1;
        o0.x = acc[i][0] + bia0.x; o0.y = acc[i][1] + bia0.y;
        o0.z = acc[i][2] + bia0.z; o0.w = acc[i][3] + bia0.w;
        o1.x = acc[i][4] + bia1.x; o1.y = acc[i][5] + bia1.y;
        o1.z = acc[i][6] + bia1.z; o1.w = acc[i][7] + bia1.w;
        *(float4*)(C + (size_t)m * N + colBase + tx * 4) = o0;
        *(float4*)(C + (size_t)m * N + colBase + 64 + tx * 4) = o1;
    }
}

// ---------------------------------------------------------------------------
// Flash attention (causal), fp32. 64x64 q/k tiles, DK=64, 256 threads.
// Layout of Q/K/V/O scratch: [B*S, D], head h occupies columns h*64..h*64+63.
// ---------------------------------------------------------------------------
#define LDP 68   // padded row stride (keeps float4 alignment, 68*4 % 16 == 0)

__global__ __launch_bounds__(256) void flash_attn_kernel(
    const float* __restrict__ Qg, const float* __restrict__ Kg,
    const float* __restrict__ Vg, float* __restrict__ Og)
{
    extern __shared__ float sm[];
    float* Qts = sm;                  // [64][LDP]  (k-major: Qts[k][m])
    float* Kts = Qts + 64 * LDP;      // [64][LDP]  (k-major: Kts[k][n])
    float* Vs  = Kts + 64 * LDP;      // [64][LDP]  (row-major: Vs[n][d])
    float* Ps  = Vs  + 64 * LDP;      // [64][LDP]  (row-major: Ps[m][n])

    const int tid = threadIdx.x;
    const int tx = tid & 15;          // n / d direction
    const int ty = tid >> 4;          // m direction
    const int qt = blockIdx.x;        // q tile index (0..31)
    const int h  = blockIdx.y;
    const int b  = blockIdx.z;

    const size_t base = (size_t)b * SS * DD + (size_t)h * DK;
    const int q0 = qt * 64;

    // Load Q tile transposed into Qts[k][m]
#pragma unroll
    for (int i = 0; i < 4; i++) {
        int fi = tid + 256 * i;       // float4 index, 1024 total
        int row = fi >> 4;            // 16 float4 per row of 64 floats
        int kc = (fi & 15) * 4;
        float4 v = *(const float4*)(Qg + base + (size_t)(q0 + row) * DD + kc);
        Qts[(kc + 0) * LDP + row] = v.x;
        Qts[(kc + 1) * LDP + row] = v.y;
        Qts[(kc + 2) * LDP + row] = v.z;
        Qts[(kc + 3) * LDP + row] = v.w;
    }

    float m_state[4], l_state[4], Oacc[4][4];
#pragma unroll
    for (int i = 0; i < 4; i++) {
        m_state[i] = -1e30f;
        l_state[i] = 0.0f;
#pragma unroll
        for (int j = 0; j < 4; j++) Oacc[i][j] = 0.0f;
    }

    for (int kt = 0; kt <= qt; kt++) {
        const int k0 = kt * 64;
        __syncthreads();  // previous tile's smem reads done; Q load visible

        // Load K (transposed) and V (direct) tiles
#pragma unroll
        for (int i = 0; i < 4; i++) {
            int fi = tid + 256 * i;
            int row = fi >> 4;
            int kc = (fi & 15) * 4;
            float4 kv = *(const float4*)(Kg + base + (size_t)(k0 + row) * DD + kc);
            Kts[(kc + 0) * LDP + row] = kv.x;
            Kts[(kc + 1) * LDP + row] = kv.y;
            Kts[(kc + 2) * LDP + row] = kv.z;
            Kts[(kc + 3) * LDP + row] = kv.w;
            float4 vv = *(const float4*)(Vg + base + (size_t)(k0 + row) * DD + kc);
            *(float4*)(Vs + row * LDP + kc) = vv;
        }
        __syncthreads();

        // S = Q @ K^T * (1/sqrt(64))
        float s[4][4];
#pragma unroll
        for (int i = 0; i < 4; i++)
#pragma unroll
            for (int j = 0; j < 4; j++) s[i][j] = 0.0f;

#pragma unroll 16
        for (int kk = 0; kk < 64; kk++) {
            float4 a = *(const float4*)(Qts + kk * LDP + ty * 4);
            float4 bq = *(const float4*)(Kts + kk * LDP + tx * 4);
            float av[4] = {a.x, a.y, a.z, a.w};
            float bv[4] = {bq.x, bq.y, bq.z, bq.w};
#pragma unroll
            for (int i = 0; i < 4; i++)
#pragma unroll
                for (int j = 0; j < 4; j++)
                    s[i][j] = fmaf(av[i], bv[j], s[i][j]);
        }

        const float scale = 0.125f;  // 1/sqrt(64)
#pragma unroll
        for (int i = 0; i < 4; i++)
#pragma unroll
            for (int j = 0; j < 4; j++) s[i][j] *= scale;

        // Causal mask on diagonal tile
        if (kt == qt) {
#pragma unroll
            for (int i = 0; i < 4; i++)
#pragma unroll
                for (int j = 0; j < 4; j++)
                    if (tx * 4 + j > ty * 4 + i) s[i][j] = -1e30f;
        }

        // Online softmax: row reductions over the 16 lanes sharing ty
#pragma unroll
        for (int i = 0; i < 4; i++) {
            float rm = fmaxf(fmaxf(s[i][0], s[i][1]), fmaxf(s[i][2], s[i][3]));
#pragma unroll
            for (int off = 8; off >= 1; off >>= 1)
                rm = fmaxf(rm, __shfl_xor_sync(0xffffffffu, rm, off));
            float newm = fmaxf(m_state[i], rm);
            float alpha = __expf(m_state[i] - newm);
            float rs = 0.0f;
#pragma unroll
            for (int j = 0; j < 4; j++) {
                float p = __expf(s[i][j] - newm);
                s[i][j] = p;
                rs += p;
            }
#pragma unroll
            for (int off = 8; off >= 1; off >>= 1)
                rs += __shfl_xor_sync(0xffffffffu, rs, off);
            l_state[i] = l_state[i] * alpha + rs;
            m_state[i] = newm;
#pragma unroll
            for (int j = 0; j < 4; j++) Oacc[i][j] *= alpha;
            // store p row chunk to Ps
            *(float4*)(Ps + (ty * 4 + i) * LDP + tx * 4) =
                make_float4(s[i][0], s[i][1], s[i][2], s[i][3]);
        }
        __syncthreads();

        // O += P @ V
#pragma unroll 8
        for (int n = 0; n < 64; n++) {
            float4 v4 = *(const float4*)(Vs + n * LDP + tx * 4);
#pragma unroll
            for (int i = 0; i < 4; i++) {
                float p = Ps[(ty * 4 + i) * LDP + n];
                Oacc[i][0] = fmaf(p, v4.x, Oacc[i][0]);
                Oacc[i][1] = fmaf(p, v4.y, Oacc[i][1]);
                Oacc[i][2] = fmaf(p, v4.z, Oacc[i][2]);
                Oacc[i][3] = fmaf(p, v4.w, Oacc[i][3]);
            }
        }
    }

    // Normalize and write out
#pragma unroll
    for (int i = 0; i < 4; i++) {
        float inv = 1.0f / l_state[i];
        float4 o;
        o.x = Oacc[i][0] * inv; o.y = Oacc[i][1] * inv;
        o.z = Oacc[i][2] * inv; o.w = Oacc[i][3] * inv;
        *(float4*)(Og + base + (size_t)(q0 + ty * 4 + i) * DD + tx * 4) = o;
    }
}

// ---------------------------------------------------------------------------
// Launch
// ---------------------------------------------------------------------------
extern "C" void kernel_launch(void* const* d_in, const int* in_sizes, int n_in,
                              void* d_out, int out_size)
{
    const float* query = (const float*)d_in[0];
    const float* key   = (const float*)d_in[1];
    const float* value = (const float*)d_in[2];
    const float* wq = (const float*)d_in[3];
    const float* bq = (const float*)d_in[4];
    const float* wk = (const float*)d_in[5];
    const float* bk = (const float*)d_in[6];
    const float* wv = (const float*)d_in[7];
    const float* bv = (const float*)d_in[8];
    const float* wo = (const float*)d_in[9];
    const float* bo = (const float*)d_in[10];
    float* out = (float*)d_out;

    float *q_s, *k_s, *v_s, *o_s;
    cudaGetSymbolAddress((void**)&q_s, g_q);
    cudaGetSymbolAddress((void**)&k_s, g_k);
    cudaGetSymbolAddress((void**)&v_s, g_v);
    cudaGetSymbolAddress((void**)&o_s, g_o);

    const int smem_attn = 4 * 64 * LDP * sizeof(float);  // 69632 bytes
    cudaFuncSetAttribute(flash_attn_kernel,
                         cudaFuncAttributeMaxDynamicSharedMemorySize, smem_attn);

    dim3 gproj(DD / 128, MROWS / 128);  // (8, 32)
    sgemm_bias_kernel<<<gproj, 256>>>(query, wq, bq, q_s, MROWS, DD, DD);
    sgemm_bias_kernel<<<gproj, 256>>>(key,   wk, bk, k_s, MROWS, DD, DD);
    sgemm_bias_kernel<<<gproj, 256>>>(value, wv, bv, v_s, MROWS, DD, DD);

    dim3 gattn(SS / 64, HH, BB);  // (32, 16, 2)
    flash_attn_kernel<<<gattn, 256, smem_attn>>>(q_s, k_s, v_s, o_s);

    sgemm_bias_kernel<<<gproj, 256>>>(o_s, wo, bo, out, MROWS, DD, DD);
}

// round 4
// speedup vs baseline: 2.6301x; 2.6301x over previous
#include <cuda_runtime.h>
#include <cstdint>

// Problem constants
#define BB 2
#define SS 2048
#define DD 1024
#define HH 16
#define DK 64
#define MROWS (BB * SS)   // 4096

// Scratch (static device globals — allocation-guard safe)
__device__ float g_q[MROWS * DD];
__device__ float g_k[MROWS * DD];
__device__ float g_v[MROWS * DD];
__device__ float g_o[MROWS * DD];

// ---------------------------------------------------------------------------
// Helpers
// ---------------------------------------------------------------------------
static __device__ __forceinline__ uint32_t f2tf32(float x) {
    uint32_t u;
    asm("cvt.rna.tf32.f32 %0, %1;" : "=r"(u) : "f"(x));
    return u;
}

// D += A @ B for one m16n8k8 tf32 tile. c: 4 fp32, a: 4 b32 (tf32), b: 2 b32.
static __device__ __forceinline__ void mma_tf32(float c[4], const uint32_t a[4],
                                                uint32_t b0, uint32_t b1) {
    asm volatile(
        "mma.sync.aligned.m16n8k8.row.col.f32.tf32.tf32.f32 "
        "{%0,%1,%2,%3}, {%4,%5,%6,%7}, {%8,%9}, {%0,%1,%2,%3};"
        : "+f"(c[0]), "+f"(c[1]), "+f"(c[2]), "+f"(c[3])
        : "r"(a[0]), "r"(a[1]), "r"(a[2]), "r"(a[3]), "r"(b0), "r"(b1));
}

// ---------------------------------------------------------------------------
// tf32 mma.sync GEMM: C[M,N] = A[M,K] @ W[N,K]^T + bias[N]
// 128x128 tile, BK=16, 256 threads (8 warps as 4(m) x 2(n), warp tile 32x64).
// ---------------------------------------------------------------------------
#define BK 16
#define APAD 20   // smem row stride in 4B words (16 + 4) -> conflict-free frags

__global__ __launch_bounds__(256, 2) void gemm_mma_kernel(
    const float* __restrict__ A, const float* __restrict__ W,
    const float* __restrict__ bias, float* __restrict__ C,
    int M, int N, int K)
{
    __shared__ uint32_t As[2][128 * APAD];
    __shared__ uint32_t Bs[2][128 * APAD];

    const int tid = threadIdx.x;
    const int lane = tid & 31;
    const int wid = tid >> 5;
    const int wm = wid & 3;          // 0..3 -> 32-row slice
    const int wn = wid >> 2;         // 0..1 -> 64-col slice
    const int l4 = lane >> 2;        // 0..7
    const int lm = lane & 3;         // 0..3
    const int rowBase = blockIdx.y * 128;
    const int colBase = blockIdx.x * 128;

    float acc[2][8][4];
#pragma unroll
    for (int mt = 0; mt < 2; mt++)
#pragma unroll
        for (int nt = 0; nt < 8; nt++)
#pragma unroll
            for (int r = 0; r < 4; r++) acc[mt][nt][r] = 0.0f;

    // global load mapping: 512 float4 per matrix per chunk; 2 each per thread
    const int grow0 = tid >> 1;           // rows 0..127 (fi = tid + 256*i -> row=fi>>2)
    float4 ra[2], rb[2];

    auto loadg = [&](int ic) {
        const int kOff = ic * BK;
#pragma unroll
        for (int i = 0; i < 2; i++) {
            int fi = tid + 256 * i;
            int row = fi >> 2;
            int k4 = fi & 3;
            ra[i] = *(const float4*)(A + (size_t)(rowBase + row) * K + kOff + k4 * 4);
            rb[i] = *(const float4*)(W + (size_t)(colBase + row) * K + kOff + k4 * 4);
        }
    };

    loadg(0);
    const int nChunks = K / BK;   // 64

    for (int ic = 0; ic < nChunks; ic++) {
        const int buf = ic & 1;
        // store prefetched regs -> smem (tf32)
#pragma unroll
        for (int i = 0; i < 2; i++) {
            int fi = tid + 256 * i;
            int row = fi >> 2;
            int k4 = fi & 3;
            uint32_t* da = &As[buf][row * APAD + k4 * 4];
            da[0] = f2tf32(ra[i].x); da[1] = f2tf32(ra[i].y);
            da[2] = f2tf32(ra[i].z); da[3] = f2tf32(ra[i].w);
            uint32_t* db = &Bs[buf][row * APAD + k4 * 4];
            db[0] = f2tf32(rb[i].x); db[1] = f2tf32(rb[i].y);
            db[2] = f2tf32(rb[i].z); db[3] = f2tf32(rb[i].w);
        }
        __syncthreads();

        if (ic + 1 < nChunks) loadg(ic + 1);

#pragma unroll
        for (int ks = 0; ks < 2; ks++) {
            const int kb = ks * 8;
            uint32_t af[2][4];
#pragma unroll
            for (int mt = 0; mt < 2; mt++) {
                int r = wm * 32 + mt * 16 + l4;
                af[mt][0] = As[buf][r * APAD + kb + lm];
                af[mt][1] = As[buf][(r + 8) * APAD + kb + lm];
                af[mt][2] = As[buf][r * APAD + kb + lm + 4];
                af[mt][3] = As[buf][(r + 8) * APAD + kb + lm + 4];
            }
#pragma unroll
            for (int nt = 0; nt < 8; nt++) {
                int c = wn * 64 + nt * 8 + l4;
                uint32_t b0 = Bs[buf][c * APAD + kb + lm];
                uint32_t b1 = Bs[buf][c * APAD + kb + lm + 4];
                mma_tf32(acc[0][nt], af[0], b0, b1);
                mma_tf32(acc[1][nt], af[1], b0, b1);
            }
        }
    }

    // epilogue: bias + store (float2 per c0/c1 pair)
#pragma unroll
    for (int nt = 0; nt < 8; nt++) {
        int c = colBase + wn * 64 + nt * 8 + 2 * lm;
        float2 bv = *(const float2*)(bias + c);
#pragma unroll
        for (int mt = 0; mt < 2; mt++) {
            int r = rowBase + wm * 32 + mt * 16 + l4;
            float2 o0 = make_float2(acc[mt][nt][0] + bv.x, acc[mt][nt][1] + bv.y);
            float2 o1 = make_float2(acc[mt][nt][2] + bv.x, acc[mt][nt][3] + bv.y);
            *(float2*)(C + (size_t)r * N + c) = o0;
            *(float2*)(C + (size_t)(r + 8) * N + c) = o1;
        }
    }
}

// ---------------------------------------------------------------------------
// Flash attention (causal) with tf32 mma.sync.
// Block: 256 threads (8 warps), 128 q rows (16 per warp), 64-key tiles, DK=64.
// ---------------------------------------------------------------------------
#define FS 68   // smem stride (words) for Ks/Vt/Ps — conflict-free frag loads

__global__ __launch_bounds__(256) void flash_mma_kernel(
    const float* __restrict__ Qg, const float* __restrict__ Kg,
    const float* __restrict__ Vg, float* __restrict__ Og)
{
    extern __shared__ uint32_t sm[];
    uint32_t* Ks = sm;                  // [64][FS]  (n, k)
    uint32_t* Vt = sm + 64 * FS;        // [64][FS]  (d, n)  (V transposed)
    uint32_t* Ps = sm + 2 * 64 * FS;    // [128][FS] (m, n)  tf32 P

    const int tid = threadIdx.x;
    const int lane = tid & 31;
    const int wid = tid >> 5;
    const int l4 = lane >> 2;
    const int lm = lane & 3;

    const int qt = blockIdx.x;
    const int h  = blockIdx.y;
    const int b  = blockIdx.z;
    const int q0 = qt * 128;

    const size_t base = (size_t)b * SS * DD + (size_t)h * DK;

    const int gr0 = q0 + wid * 16 + l4;   // global q row (c0/c1); gr0+8 for c2/c3
    const int prow = wid * 16 + l4;       // local row in Ps

    // Q fragments in registers: 16 rows x 64 k per warp
    uint32_t qf[8][4];
#pragma unroll
    for (int ks = 0; ks < 8; ks++) {
        const float* q0p = Qg + base + (size_t)gr0 * DD;
        const float* q1p = Qg + base + (size_t)(gr0 + 8) * DD;
        qf[ks][0] = f2tf32(q0p[ks * 8 + lm]);
        qf[ks][1] = f2tf32(q1p[ks * 8 + lm]);
        qf[ks][2] = f2tf32(q0p[ks * 8 + lm + 4]);
        qf[ks][3] = f2tf32(q1p[ks * 8 + lm + 4]);
    }

    float oacc[8][4];
#pragma unroll
    for (int dt = 0; dt < 8; dt++)
#pragma unroll
        for (int r = 0; r < 4; r++) oacc[dt][r] = 0.0f;
    float m0 = -1e30f, m1 = -1e30f, l0 = 0.0f, l1 = 0.0f;

    const int nkt = 2 * qt + 2;
    for (int kt = 0; kt < nkt; kt++) {
        const int k0 = kt * 64;
        __syncthreads();   // previous iteration's smem reads complete

        // K tile: [n][k], float4 loads, tf32 stores
#pragma unroll
        for (int i = 0; i < 4; i++) {
            int fi = tid + 256 * i;
            int row = fi >> 4;
            int c4 = (fi & 15) * 4;
            float4 kv = *(const float4*)(Kg + base + (size_t)(k0 + row) * DD + c4);
            uint32_t* dst = Ks + row * FS + c4;
            dst[0] = f2tf32(kv.x); dst[1] = f2tf32(kv.y);
            dst[2] = f2tf32(kv.z); dst[3] = f2tf32(kv.w);
        }
        // V tile transposed: [d][n], coalesced scalar loads
#pragma unroll
        for (int i = 0; i < 16; i++) {
            int fi = tid + 256 * i;
            int row = fi >> 6;      // n (seq)
            int d = fi & 63;        // headdim
            float v = Vg[base + (size_t)(k0 + row) * DD + d];
            Vt[d * FS + row] = f2tf32(v);
        }
        __syncthreads();

        // S = Q @ K^T
        float sf[8][4];
#pragma unroll
        for (int nt = 0; nt < 8; nt++)
#pragma unroll
            for (int r = 0; r < 4; r++) sf[nt][r] = 0.0f;

#pragma unroll
        for (int ks = 0; ks < 8; ks++) {
#pragma unroll
            for (int nt = 0; nt < 8; nt++) {
                uint32_t b0 = Ks[(nt * 8 + l4) * FS + ks * 8 + lm];
                uint32_t b1 = Ks[(nt * 8 + l4) * FS + ks * 8 + lm + 4];
                mma_tf32(sf[nt], qf[ks], b0, b1);
            }
        }

        const float scale = 0.125f;   // 1/sqrt(64)
#pragma unroll
        for (int nt = 0; nt < 8; nt++)
#pragma unroll
            for (int r = 0; r < 4; r++) sf[nt][r] *= scale;

        // causal mask (warp-uniform predicate on whether this tile needs it)
        if (k0 + 63 > q0 + wid * 16) {
#pragma unroll
            for (int nt = 0; nt < 8; nt++) {
                int c = k0 + nt * 8 + 2 * lm;
                if (c     > gr0)     sf[nt][0] = -1e30f;
                if (c + 1 > gr0)     sf[nt][1] = -1e30f;
                if (c     > gr0 + 8) sf[nt][2] = -1e30f;
                if (c + 1 > gr0 + 8) sf[nt][3] = -1e30f;
            }
        }

        // online softmax (rows gr0 and gr0+8), reduce over 4 lanes of the row
        float rm0 = -1e30f, rm1 = -1e30f;
#pragma unroll
        for (int nt = 0; nt < 8; nt++) {
            rm0 = fmaxf(rm0, fmaxf(sf[nt][0], sf[nt][1]));
            rm1 = fmaxf(rm1, fmaxf(sf[nt][2], sf[nt][3]));
        }
#pragma unroll
        for (int off = 1; off <= 2; off <<= 1) {
            rm0 = fmaxf(rm0, __shfl_xor_sync(0xffffffffu, rm0, off));
            rm1 = fmaxf(rm1, __shfl_xor_sync(0xffffffffu, rm1, off));
        }
        float nm0 = fmaxf(m0, rm0), nm1 = fmaxf(m1, rm1);
        float a0 = __expf(m0 - nm0), a1 = __expf(m1 - nm1);
        float rs0 = 0.0f, rs1 = 0.0f;
#pragma unroll
        for (int nt = 0; nt < 8; nt++) {
            sf[nt][0] = __expf(sf[nt][0] - nm0);
            sf[nt][1] = __expf(sf[nt][1] - nm0);
            sf[nt][2] = __expf(sf[nt][2] - nm1);
            sf[nt][3] = __expf(sf[nt][3] - nm1);
            rs0 += sf[nt][0] + sf[nt][1];
            rs1 += sf[nt][2] + sf[nt][3];
        }
#pragma unroll
        for (int off = 1; off <= 2; off <<= 1) {
            rs0 += __shfl_xor_sync(0xffffffffu, rs0, off);
            rs1 += __shfl_xor_sync(0xffffffffu, rs1, off);
        }
        l0 = l0 * a0 + rs0;  m0 = nm0;
        l1 = l1 * a1 + rs1;  m1 = nm1;
#pragma unroll
        for (int dt = 0; dt < 8; dt++) {
            oacc[dt][0] *= a0; oacc[dt][1] *= a0;
            oacc[dt][2] *= a1; oacc[dt][3] *= a1;
        }

        // P -> smem (tf32); only this warp's rows, so warp-sync suffices
#pragma unroll
        for (int nt = 0; nt < 8; nt++) {
            int c = nt * 8 + 2 * lm;
            Ps[prow * FS + c]           = f2tf32(sf[nt][0]);
            Ps[prow * FS + c + 1]       = f2tf32(sf[nt][1]);
            Ps[(prow + 8) * FS + c]     = f2tf32(sf[nt][2]);
            Ps[(prow + 8) * FS + c + 1] = f2tf32(sf[nt][3]);
        }
        __syncwarp();

        // O += P @ V  (A = P rows of this warp, B = Vt)
#pragma unroll
        for (int ks = 0; ks < 8; ks++) {
            uint32_t af[4];
            af[0] = Ps[prow * FS + ks * 8 + lm];
            af[1] = Ps[(prow + 8) * FS + ks * 8 + lm];
            af[2] = Ps[prow * FS + ks * 8 + lm + 4];
            af[3] = Ps[(prow + 8) * FS + ks * 8 + lm + 4];
#pragma unroll
            for (int dt = 0; dt < 8; dt++) {
                uint32_t b0 = Vt[(dt * 8 + l4) * FS + ks * 8 + lm];
                uint32_t b1 = Vt[(dt * 8 + l4) * FS + ks * 8 + lm + 4];
                mma_tf32(oacc[dt], af, b0, b1);
            }
        }
    }

    // finalize: normalize rows and store
    float inv0 = 1.0f / l0, inv1 = 1.0f / l1;
#pragma unroll
    for (int dt = 0; dt < 8; dt++) {
        int d = dt * 8 + 2 * lm;
        float2 o0 = make_float2(oacc[dt][0] * inv0, oacc[dt][1] * inv0);
        float2 o1 = make_float2(oacc[dt][2] * inv1, oacc[dt][3] * inv1);
        *(float2*)(Og + base + (size_t)gr0 * DD + d) = o0;
        *(float2*)(Og + base + (size_t)(gr0 + 8) * DD + d) = o1;
    }
}

// ---------------------------------------------------------------------------
// Launch
// ---------------------------------------------------------------------------
extern "C" void kernel_launch(void* const* d_in, const int* in_sizes, int n_in,
                              void* d_out, int out_size)
{
    const float* query = (const float*)d_in[0];
    const float* key   = (const float*)d_in[1];
    const float* value = (const float*)d_in[2];
    const float* wq = (const float*)d_in[3];
    const float* bq = (const float*)d_in[4];
    const float* wk = (const float*)d_in[5];
    const float* bk = (const float*)d_in[6];
    const float* wv = (const float*)d_in[7];
    const float* bv = (const float*)d_in[8];
    const float* wo = (const float*)d_in[9];
    const float* bo = (const float*)d_in[10];
    float* out = (float*)d_out;

    float *q_s, *k_s, *v_s, *o_s;
    cudaGetSymbolAddress((void**)&q_s, g_q);
    cudaGetSymbolAddress((void**)&k_s, g_k);
    cudaGetSymbolAddress((void**)&v_s, g_v);
    cudaGetSymbolAddress((void**)&o_s, g_o);

    const int smem_attn = (2 * 64 + 128) * FS * sizeof(uint32_t);  // 69632 B
    cudaFuncSetAttribute(flash_mma_kernel,
                         cudaFuncAttributeMaxDynamicSharedMemorySize, smem_attn);

    dim3 gproj(DD / 128, MROWS / 128);  // (8, 32)
    gemm_mma_kernel<<<gproj, 256>>>(query, wq, bq, q_s, MROWS, DD, DD);
    gemm_mma_kernel<<<gproj, 256>>>(key,   wk, bk, k_s, MROWS, DD, DD);
    gemm_mma_kernel<<<gproj, 256>>>(value, wv, bv, v_s, MROWS, DD, DD);

    dim3 gattn(SS / 128, HH, BB);  // (16, 16, 2)
    flash_mma_kernel<<<gattn, 256, smem_attn>>>(q_s, k_s, v_s, o_s);

    gemm_mma_kernel<<<gproj, 256>>>(o_s, wo, bo, out, MROWS, DD, DD);
}

// round 5
// speedup vs baseline: 3.1275x; 1.1891x over previous
#include <cuda_runtime.h>
#include <cstdint>

// Problem constants
#define BB 2
#define SS 2048
#define DD 1024
#define HH 16
#define DK 64
#define MROWS (BB * SS)   // 4096

// Scratch (static device globals — allocation-guard safe)
__device__ float g_q[MROWS * DD];
__device__ float g_k[MROWS * DD];
__device__ float g_v[MROWS * DD];
__device__ float g_o[MROWS * DD];

// ---------------------------------------------------------------------------
// Helpers
// ---------------------------------------------------------------------------
static __device__ __forceinline__ uint32_t f2tf32(float x) {
    uint32_t u;
    asm("cvt.rna.tf32.f32 %0, %1;" : "=r"(u) : "f"(x));
    return u;
}

static __device__ __forceinline__ uint32_t cvta_smem(const void* p) {
    uint32_t a;
    asm("{ .reg .u64 t; cvta.to.shared.u64 t, %1; cvt.u32.u64 %0, t; }"
        : "=r"(a) : "l"(p));
    return a;
}

// m16n8k8 tf32 MMA: c += a @ b
static __device__ __forceinline__ void mma_tf32(float c[4], const uint32_t a[4],
                                                uint32_t b0, uint32_t b1) {
    asm volatile(
        "mma.sync.aligned.m16n8k8.row.col.f32.tf32.tf32.f32 "
        "{%0,%1,%2,%3}, {%4,%5,%6,%7}, {%8,%9}, {%0,%1,%2,%3};"
        : "+f"(c[0]), "+f"(c[1]), "+f"(c[2]), "+f"(c[3])
        : "r"(a[0]), "r"(a[1]), "r"(a[2]), "r"(a[3]), "r"(b0), "r"(b1));
}

static __device__ __forceinline__ void ldsm_x4(uint32_t r[4], uint32_t addr) {
    asm volatile("ldmatrix.sync.aligned.m8n8.x4.shared.b16 {%0,%1,%2,%3}, [%4];"
        : "=r"(r[0]), "=r"(r[1]), "=r"(r[2]), "=r"(r[3]) : "r"(addr));
}

// ---------------------------------------------------------------------------
// Fused tf32 mma.sync GEMM: C[z] = A[z] @ W[z]^T + bias[z] for z = 0..gridDim.z-1
// M=4096, N=K=1024. 128x128 tile, BK=16, 256 threads (8 warps: 4m x 2n).
// ---------------------------------------------------------------------------
#define BK 16
#define APAD 20
#define GBUF (128 * APAD)      // words per buffer

__global__ __launch_bounds__(256, 2) void gemm3_mma_kernel(
    const float* __restrict__ A0, const float* __restrict__ A1, const float* __restrict__ A2,
    const float* __restrict__ W0, const float* __restrict__ W1, const float* __restrict__ W2,
    const float* __restrict__ b0p, const float* __restrict__ b1p, const float* __restrict__ b2p,
    float* __restrict__ C0, float* __restrict__ C1, float* __restrict__ C2)
{
    __shared__ uint32_t As[2][GBUF];
    __shared__ uint32_t Bs[2][GBUF];

    const int z = blockIdx.z;
    const float* A = (z == 0) ? A0 : (z == 1) ? A1 : A2;
    const float* W = (z == 0) ? W0 : (z == 1) ? W1 : W2;
    const float* bias = (z == 0) ? b0p : (z == 1) ? b1p : b2p;
    float* C = (z == 0) ? C0 : (z == 1) ? C1 : C2;

    const int tid = threadIdx.x;
    const int lane = tid & 31;
    const int wid = tid >> 5;
    const int wm = wid & 3;
    const int wn = wid >> 2;
    const int l4 = lane >> 2;
    const int lm = lane & 3;
    const int rowBase = blockIdx.y * 128;
    const int colBase = blockIdx.x * 128;

    const uint32_t asb = cvta_smem(As);
    const uint32_t bsb = cvta_smem(Bs);

    // ldmatrix lane-address offsets (bytes) within a buffer
    uint32_t aOff[2], bOff[4];
#pragma unroll
    for (int mt = 0; mt < 2; mt++)
        aOff[mt] = ((wm * 32 + mt * 16 + (lane & 15)) * APAD + ((lane >> 4) << 2)) * 4;
#pragma unroll
    for (int t = 0; t < 4; t++)
        bOff[t] = ((wn * 64 + t * 16 + (lane & 7) + 8 * ((lane >> 4) & 1)) * APAD
                   + 4 * ((lane >> 3) & 1)) * 4;

    float acc[2][8][4];
#pragma unroll
    for (int mt = 0; mt < 2; mt++)
#pragma unroll
        for (int nt = 0; nt < 8; nt++)
#pragma unroll
            for (int r = 0; r < 4; r++) acc[mt][nt][r] = 0.0f;

    float4 ra[2], rb[2];
    auto loadg = [&](int ic) {
        const int kOff = ic * BK;
#pragma unroll
        for (int i = 0; i < 2; i++) {
            int fi = tid + 256 * i;
            int row = fi >> 2;
            int k4 = fi & 3;
            ra[i] = *(const float4*)(A + (size_t)(rowBase + row) * DD + kOff + k4 * 4);
            rb[i] = *(const float4*)(W + (size_t)(colBase + row) * DD + kOff + k4 * 4);
        }
    };

    loadg(0);
    const int nChunks = DD / BK;   // 64

    for (int ic = 0; ic < nChunks; ic++) {
        const int buf = ic & 1;
        const uint32_t bufB = buf * (GBUF * 4);
#pragma unroll
        for (int i = 0; i < 2; i++) {
            int fi = tid + 256 * i;
            int row = fi >> 2;
            int k4 = fi & 3;
            uint32_t* da = &As[buf][row * APAD + k4 * 4];
            da[0] = f2tf32(ra[i].x); da[1] = f2tf32(ra[i].y);
            da[2] = f2tf32(ra[i].z); da[3] = f2tf32(ra[i].w);
            uint32_t* db = &Bs[buf][row * APAD + k4 * 4];
            db[0] = f2tf32(rb[i].x); db[1] = f2tf32(rb[i].y);
            db[2] = f2tf32(rb[i].z); db[3] = f2tf32(rb[i].w);
        }
        __syncthreads();

        if (ic + 1 < nChunks) loadg(ic + 1);

#pragma unroll
        for (int ks = 0; ks < 2; ks++) {
            const uint32_t kbB = ks * 32;   // 8 words
            uint32_t af0[4], af1[4];
            ldsm_x4(af0, asb + bufB + aOff[0] + kbB);
            ldsm_x4(af1, asb + bufB + aOff[1] + kbB);
#pragma unroll
            for (int t = 0; t < 4; t++) {
                uint32_t bb[4];
                ldsm_x4(bb, bsb + bufB + bOff[t] + kbB);
                mma_tf32(acc[0][2 * t],     af0, bb[0], bb[1]);
                mma_tf32(acc[1][2 * t],     af1, bb[0], bb[1]);
                mma_tf32(acc[0][2 * t + 1], af0, bb[2], bb[3]);
                mma_tf32(acc[1][2 * t + 1], af1, bb[2], bb[3]);
            }
        }
        __syncthreads();
    }

    // epilogue: bias + store
#pragma unroll
    for (int nt = 0; nt < 8; nt++) {
        int c = colBase + wn * 64 + nt * 8 + 2 * lm;
        float2 bv = *(const float2*)(bias + c);
#pragma unroll
        for (int mt = 0; mt < 2; mt++) {
            int r = rowBase + wm * 32 + mt * 16 + l4;
            float2 o0 = make_float2(acc[mt][nt][0] + bv.x, acc[mt][nt][1] + bv.y);
            float2 o1 = make_float2(acc[mt][nt][2] + bv.x, acc[mt][nt][3] + bv.y);
            *(float2*)(C + (size_t)r * DD + c) = o0;
            *(float2*)(C + (size_t)(r + 8) * DD + c) = o1;
        }
    }
}

// ---------------------------------------------------------------------------
// Flash attention (causal), tf32 mma.sync, ldmatrix frags, reg-prefetched K/V.
// 256 threads, 128 q rows per CTA, 64-key tiles, DK=64.
// ---------------------------------------------------------------------------
#define FS 68

__global__ __launch_bounds__(256) void flash_mma_kernel(
    const float* __restrict__ Qg, const float* __restrict__ Kg,
    const float* __restrict__ Vg, float* __restrict__ Og)
{
    extern __shared__ uint32_t sm[];
    uint32_t* Ks = sm;                  // [64][FS]  (n, k)
    uint32_t* Vt = sm + 64 * FS;        // [64][FS]  (d, n)
    uint32_t* Ps = sm + 2 * 64 * FS;    // [128][FS] (m, n)

    const int tid = threadIdx.x;
    const int lane = tid & 31;
    const int wid = tid >> 5;
    const int l4 = lane >> 2;
    const int lm = lane & 3;

    const int qt = (gridDim.x - 1) - blockIdx.x;   // heavy tiles first
    const int h  = blockIdx.y;
    const int b  = blockIdx.z;
    const int q0 = qt * 128;

    const size_t base = (size_t)b * SS * DD + (size_t)h * DK;

    const int gr0 = q0 + wid * 16 + l4;
    const int prow = wid * 16 + l4;

    const uint32_t ksb = cvta_smem(Ks);
    const uint32_t vtb = cvta_smem(Vt);
    const uint32_t psb = cvta_smem(Ps);

    // ldmatrix lane-address offsets (bytes)
    uint32_t kvOff[4];
#pragma unroll
    for (int t = 0; t < 4; t++)
        kvOff[t] = ((t * 16 + (lane & 7) + 8 * ((lane >> 4) & 1)) * FS
                    + 4 * ((lane >> 3) & 1)) * 4;
    const uint32_t pOff = ((wid * 16 + (lane & 15)) * FS + ((lane >> 4) << 2)) * 4;

    // Q fragments in registers
    uint32_t qf[8][4];
#pragma unroll
    for (int ks = 0; ks < 8; ks++) {
        const float* q0p = Qg + base + (size_t)gr0 * DD;
        const float* q1p = Qg + base + (size_t)(gr0 + 8) * DD;
        qf[ks][0] = f2tf32(q0p[ks * 8 + lm]);
        qf[ks][1] = f2tf32(q1p[ks * 8 + lm]);
        qf[ks][2] = f2tf32(q0p[ks * 8 + lm + 4]);
        qf[ks][3] = f2tf32(q1p[ks * 8 + lm + 4]);
    }

    float oacc[8][4];
#pragma unroll
    for (int dt = 0; dt < 8; dt++)
#pragma unroll
        for (int r = 0; r < 4; r++) oacc[dt][r] = 0.0f;
    float m0 = -1e30f, m1 = -1e30f, l0 = 0.0f, l1 = 0.0f;

    // K/V tile register prefetch buffers
    float4 kr[4];
    float vr[16];
    auto load_kv = [&](int kt) {
        const int k0 = kt * 64;
#pragma unroll
        for (int i = 0; i < 4; i++) {
            int fi = tid + 256 * i;
            int row = fi >> 4;
            int c4 = (fi & 15) * 4;
            kr[i] = *(const float4*)(Kg + base + (size_t)(k0 + row) * DD + c4);
        }
#pragma unroll
        for (int i = 0; i < 16; i++) {
            int fi = tid + 256 * i;
            int row = fi >> 6;
            int d = fi & 63;
            vr[i] = Vg[base + (size_t)(k0 + row) * DD + d];
        }
    };

    load_kv(0);
    const int nkt = 2 * qt + 2;
    for (int kt = 0; kt < nkt; kt++) {
        const int k0 = kt * 64;
        __syncthreads();   // prev iteration's smem reads complete

        // store prefetched K/V regs -> smem (tf32)
#pragma unroll
        for (int i = 0; i < 4; i++) {
            int fi = tid + 256 * i;
            int row = fi >> 4;
            int c4 = (fi & 15) * 4;
            uint32_t* dst = Ks + row * FS + c4;
            dst[0] = f2tf32(kr[i].x); dst[1] = f2tf32(kr[i].y);
            dst[2] = f2tf32(kr[i].z); dst[3] = f2tf32(kr[i].w);
        }
#pragma unroll
        for (int i = 0; i < 16; i++) {
            int fi = tid + 256 * i;
            int row = fi >> 6;
            int d = fi & 63;
            Vt[d * FS + row] = f2tf32(vr[i]);
        }
        __syncthreads();

        if (kt + 1 < nkt) load_kv(kt + 1);   // overlap LDG with MMA phase

        // S = Q @ K^T
        float sf[8][4];
#pragma unroll
        for (int nt = 0; nt < 8; nt++)
#pragma unroll
            for (int r = 0; r < 4; r++) sf[nt][r] = 0.0f;

#pragma unroll
        for (int ks = 0; ks < 8; ks++) {
            const uint32_t kbB = ks * 32;
#pragma unroll
            for (int t = 0; t < 4; t++) {
                uint32_t bb[4];
                ldsm_x4(bb, ksb + kvOff[t] + kbB);
                mma_tf32(sf[2 * t],     qf[ks], bb[0], bb[1]);
                mma_tf32(sf[2 * t + 1], qf[ks], bb[2], bb[3]);
            }
        }

        const float scale = 0.125f;
#pragma unroll
        for (int nt = 0; nt < 8; nt++)
#pragma unroll
            for (int r = 0; r < 4; r++) sf[nt][r] *= scale;

        if (k0 + 63 > q0 + wid * 16) {
#pragma unroll
            for (int nt = 0; nt < 8; nt++) {
                int c = k0 + nt * 8 + 2 * lm;
                if (c     > gr0)     sf[nt][0] = -1e30f;
                if (c + 1 > gr0)     sf[nt][1] = -1e30f;
                if (c     > gr0 + 8) sf[nt][2] = -1e30f;
                if (c + 1 > gr0 + 8) sf[nt][3] = -1e30f;
            }
        }

        // online softmax
        float rm0 = -1e30f, rm1 = -1e30f;
#pragma unroll
        for (int nt = 0; nt < 8; nt++) {
            rm0 = fmaxf(rm0, fmaxf(sf[nt][0], sf[nt][1]));
            rm1 = fmaxf(rm1, fmaxf(sf[nt][2], sf[nt][3]));
        }
#pragma unroll
        for (int off = 1; off <= 2; off <<= 1) {
            rm0 = fmaxf(rm0, __shfl_xor_sync(0xffffffffu, rm0, off));
            rm1 = fmaxf(rm1, __shfl_xor_sync(0xffffffffu, rm1, off));
        }
        float nm0 = fmaxf(m0, rm0), nm1 = fmaxf(m1, rm1);
        float a0 = __expf(m0 - nm0), a1 = __expf(m1 - nm1);
        float rs0 = 0.0f, rs1 = 0.0f;
#pragma unroll
        for (int nt = 0; nt < 8; nt++) {
            sf[nt][0] = __expf(sf[nt][0] - nm0);
            sf[nt][1] = __expf(sf[nt][1] - nm0);
            sf[nt][2] = __expf(sf[nt][2] - nm1);
            sf[nt][3] = __expf(sf[nt][3] - nm1);
            rs0 += sf[nt][0] + sf[nt][1];
            rs1 += sf[nt][2] + sf[nt][3];
        }
#pragma unroll
        for (int off = 1; off <= 2; off <<= 1) {
            rs0 += __shfl_xor_sync(0xffffffffu, rs0, off);
            rs1 += __shfl_xor_sync(0xffffffffu, rs1, off);
        }
        l0 = l0 * a0 + rs0;  m0 = nm0;
        l1 = l1 * a1 + rs1;  m1 = nm1;
#pragma unroll
        for (int dt = 0; dt < 8; dt++) {
            oacc[dt][0] *= a0; oacc[dt][1] *= a0;
            oacc[dt][2] *= a1; oacc[dt][3] *= a1;
        }

        // P -> smem (tf32), warp-private rows
#pragma unroll
        for (int nt = 0; nt < 8; nt++) {
            int c = nt * 8 + 2 * lm;
            uint32_t p0 = f2tf32(sf[nt][0]), p1 = f2tf32(sf[nt][1]);
            uint32_t p2 = f2tf32(sf[nt][2]), p3 = f2tf32(sf[nt][3]);
            *(uint2*)&Ps[prow * FS + c]       = make_uint2(p0, p1);
            *(uint2*)&Ps[(prow + 8) * FS + c] = make_uint2(p2, p3);
        }
        __syncwarp();

        // O += P @ V
#pragma unroll
        for (int ks = 0; ks < 8; ks++) {
            const uint32_t kbB = ks * 32;
            uint32_t af[4];
            ldsm_x4(af, psb + pOff + kbB);
#pragma unroll
            for (int t = 0; t < 4; t++) {
                uint32_t bb[4];
                ldsm_x4(bb, vtb + kvOff[t] + kbB);
                mma_tf32(oacc[2 * t],     af, bb[0], bb[1]);
                mma_tf32(oacc[2 * t + 1], af, bb[2], bb[3]);
            }
        }
    }

    float inv0 = 1.0f / l0, inv1 = 1.0f / l1;
#pragma unroll
    for (int dt = 0; dt < 8; dt++) {
        int d = dt * 8 + 2 * lm;
        float2 o0 = make_float2(oacc[dt][0] * inv0, oacc[dt][1] * inv0);
        float2 o1 = make_float2(oacc[dt][2] * inv1, oacc[dt][3] * inv1);
        *(float2*)(Og + base + (size_t)gr0 * DD + d) = o0;
        *(float2*)(Og + base + (size_t)(gr0 + 8) * DD + d) = o1;
    }
}

// ---------------------------------------------------------------------------
// Launch
// ---------------------------------------------------------------------------
extern "C" void kernel_launch(void* const* d_in, const int* in_sizes, int n_in,
                              void* d_out, int out_size)
{
    const float* query = (const float*)d_in[0];
    const float* key   = (const float*)d_in[1];
    const float* value = (const float*)d_in[2];
    const float* wq = (const float*)d_in[3];
    const float* bq = (const float*)d_in[4];
    const float* wk = (const float*)d_in[5];
    const float* bk = (const float*)d_in[6];
    const float* wv = (const float*)d_in[7];
    const float* bv = (const float*)d_in[8];
    const float* wo = (const float*)d_in[9];
    const float* bo = (const float*)d_in[10];
    float* out = (float*)d_out;

    float *q_s, *k_s, *v_s, *o_s;
    cudaGetSymbolAddress((void**)&q_s, g_q);
    cudaGetSymbolAddress((void**)&k_s, g_k);
    cudaGetSymbolAddress((void**)&v_s, g_v);
    cudaGetSymbolAddress((void**)&o_s, g_o);

    const int smem_attn = (2 * 64 + 128) * FS * sizeof(uint32_t);  // 69632 B
    cudaFuncSetAttribute(flash_mma_kernel,
                         cudaFuncAttributeMaxDynamicSharedMemorySize, smem_attn);

    dim3 gproj3(DD / 128, MROWS / 128, 3);  // fused q/k/v projections
    gemm3_mma_kernel<<<gproj3, 256>>>(query, key, value, wq, wk, wv,
                                      bq, bk, bv, q_s, k_s, v_s);

    dim3 gattn(SS / 128, HH, BB);  // (16, 16, 2)
    flash_mma_kernel<<<gattn, 256, smem_attn>>>(q_s, k_s, v_s, o_s);

    dim3 gproj1(DD / 128, MROWS / 128, 1);  // output projection
    gemm3_mma_kernel<<<gproj1, 256>>>(o_s, o_s, o_s, wo, wo, wo,
                                      bo, bo, bo, out, out, out);
}

// round 6
// speedup vs baseline: 3.2745x; 1.0470x over previous
#include <cuda_runtime.h>
#include <cstdint>

// Problem constants
#define BB 2
#define SS 2048
#define DD 1024
#define HH 16
#define DK 64
#define MROWS (BB * SS)   // 4096

// Scratch (static device globals — allocation-guard safe)
__device__ float g_q[MROWS * DD];
__device__ float g_k[MROWS * DD];
__device__ float g_v[MROWS * DD];
__device__ float g_o[MROWS * DD];

// ---------------------------------------------------------------------------
// Helpers
// ---------------------------------------------------------------------------
static __device__ __forceinline__ uint32_t f2tf32(float x) {
    uint32_t u;
    asm("cvt.rna.tf32.f32 %0, %1;" : "=r"(u) : "f"(x));
    return u;
}

static __device__ __forceinline__ uint32_t cvta_smem(const void* p) {
    uint32_t a;
    asm("{ .reg .u64 t; cvta.to.shared.u64 t, %1; cvt.u32.u64 %0, t; }"
        : "=r"(a) : "l"(p));
    return a;
}

// m16n8k8 tf32 MMA: c += a @ b
static __device__ __forceinline__ void mma_tf32(float c[4], const uint32_t a[4],
                                                uint32_t b0, uint32_t b1) {
    asm volatile(
        "mma.sync.aligned.m16n8k8.row.col.f32.tf32.tf32.f32 "
        "{%0,%1,%2,%3}, {%4,%5,%6,%7}, {%8,%9}, {%0,%1,%2,%3};"
        : "+f"(c[0]), "+f"(c[1]), "+f"(c[2]), "+f"(c[3])
        : "r"(a[0]), "r"(a[1]), "r"(a[2]), "r"(a[3]), "r"(b0), "r"(b1));
}

static __device__ __forceinline__ void ldsm_x4(uint32_t r[4], uint32_t addr) {
    asm volatile("ldmatrix.sync.aligned.m8n8.x4.shared.b16 {%0,%1,%2,%3}, [%4];"
        : "=r"(r[0]), "=r"(r[1]), "=r"(r[2]), "=r"(r[3]) : "r"(addr));
}

// ---------------------------------------------------------------------------
// Fused tf32 mma.sync GEMM: C[z] = A[z] @ W[z]^T + bias[z], z = blockIdx.z
// M=4096, N=K=1024. CTA tile 128x128, BK=16, 128 threads (4 warps, 64x64 each).
// ---------------------------------------------------------------------------
#define BK 16
#define APAD 20
#define GBUF (128 * APAD)      // words per buffer

__global__ __launch_bounds__(128, 2) void gemm3_mma_kernel(
    const float* __restrict__ A0, const float* __restrict__ A1, const float* __restrict__ A2,
    const float* __restrict__ W0, const float* __restrict__ W1, const float* __restrict__ W2,
    const float* __restrict__ b0p, const float* __restrict__ b1p, const float* __restrict__ b2p,
    float* __restrict__ C0, float* __restrict__ C1, float* __restrict__ C2)
{
    __shared__ uint32_t As[2][GBUF];
    __shared__ uint32_t Bs[2][GBUF];

    const int z = blockIdx.z;
    const float* A = (z == 0) ? A0 : (z == 1) ? A1 : A2;
    const float* W = (z == 0) ? W0 : (z == 1) ? W1 : W2;
    const float* bias = (z == 0) ? b0p : (z == 1) ? b1p : b2p;
    float* C = (z == 0) ? C0 : (z == 1) ? C1 : C2;

    const int tid = threadIdx.x;
    const int lane = tid & 31;
    const int wid = tid >> 5;        // 0..3
    const int wm = wid & 1;          // 64-row slice
    const int wn = wid >> 1;         // 64-col slice
    const int l4 = lane >> 2;
    const int lm = lane & 3;
    const int rowBase = blockIdx.y * 128;
    const int colBase = blockIdx.x * 128;

    const uint32_t asb = cvta_smem(As);
    const uint32_t bsb = cvta_smem(Bs);

    // ldmatrix lane-address offsets (bytes) within a buffer
    uint32_t aOff[4], bOff[4];
#pragma unroll
    for (int mt = 0; mt < 4; mt++)
        aOff[mt] = ((wm * 64 + mt * 16 + (lane & 15)) * APAD + ((lane >> 4) << 2)) * 4;
#pragma unroll
    for (int t = 0; t < 4; t++)
        bOff[t] = ((wn * 64 + t * 16 + (lane & 7) + 8 * ((lane >> 4) & 1)) * APAD
                   + 4 * ((lane >> 3) & 1)) * 4;

    float acc[4][8][4];
#pragma unroll
    for (int mt = 0; mt < 4; mt++)
#pragma unroll
        for (int nt = 0; nt < 8; nt++)
#pragma unroll
            for (int r = 0; r < 4; r++) acc[mt][nt][r] = 0.0f;

    // global prefetch: 4 float4 per matrix per thread per chunk
    float4 ra[4], rb[4];
    auto loadg = [&](int ic) {
        const int kOff = ic * BK;
#pragma unroll
        for (int i = 0; i < 4; i++) {
            int fi = tid + 128 * i;
            int row = fi >> 2;
            int k4 = fi & 3;
            ra[i] = *(const float4*)(A + (size_t)(rowBase + row) * DD + kOff + k4 * 4);
            rb[i] = *(const float4*)(W + (size_t)(colBase + row) * DD + kOff + k4 * 4);
        }
    };

    loadg(0);
    const int nChunks = DD / BK;   // 64

    for (int ic = 0; ic < nChunks; ic++) {
        const int buf = ic & 1;
        const uint32_t bufB = buf * (GBUF * 4);
#pragma unroll
        for (int i = 0; i < 4; i++) {
            int fi = tid + 128 * i;
            int row = fi >> 2;
            int k4 = fi & 3;
            uint32_t* da = &As[buf][row * APAD + k4 * 4];
            da[0] = f2tf32(ra[i].x); da[1] = f2tf32(ra[i].y);
            da[2] = f2tf32(ra[i].z); da[3] = f2tf32(ra[i].w);
            uint32_t* db = &Bs[buf][row * APAD + k4 * 4];
            db[0] = f2tf32(rb[i].x); db[1] = f2tf32(rb[i].y);
            db[2] = f2tf32(rb[i].z); db[3] = f2tf32(rb[i].w);
        }
        __syncthreads();

        if (ic + 1 < nChunks) loadg(ic + 1);

#pragma unroll
        for (int ks = 0; ks < 2; ks++) {
            const uint32_t kbB = ks * 32;   // 8 words
            uint32_t af[4][4];
#pragma unroll
            for (int mt = 0; mt < 4; mt++)
                ldsm_x4(af[mt], asb + bufB + aOff[mt] + kbB);
#pragma unroll
            for (int t = 0; t < 4; t++) {
                uint32_t bb[4];
                ldsm_x4(bb, bsb + bufB + bOff[t] + kbB);
#pragma unroll
                for (int mt = 0; mt < 4; mt++) {
                    mma_tf32(acc[mt][2 * t],     af[mt], bb[0], bb[1]);
                    mma_tf32(acc[mt][2 * t + 1], af[mt], bb[2], bb[3]);
                }
            }
        }
        // no trailing sync: double-buffered smem makes the next chunk's
        // stores (to buf^1) race-free against this chunk's reads (buf)
    }

    // epilogue: bias + store
#pragma unroll
    for (int nt = 0; nt < 8; nt++) {
        int c = colBase + wn * 64 + nt * 8 + 2 * lm;
        float2 bv = *(const float2*)(bias + c);
#pragma unroll
        for (int mt = 0; mt < 4; mt++) {
            int r = rowBase + wm * 64 + mt * 16 + l4;
            float2 o0 = make_float2(acc[mt][nt][0] + bv.x, acc[mt][nt][1] + bv.y);
            float2 o1 = make_float2(acc[mt][nt][2] + bv.x, acc[mt][nt][3] + bv.y);
            *(float2*)(C + (size_t)r * DD + c) = o0;
            *(float2*)(C + (size_t)(r + 8) * DD + c) = o1;
        }
    }
}

// ---------------------------------------------------------------------------
// Flash attention (causal), tf32 mma.sync, ldmatrix frags.
// Double-buffered K/V smem, one __syncthreads per tile.
// 256 threads, 128 q rows per CTA, 64-key tiles, DK=64.
// ---------------------------------------------------------------------------
#define FS 68

__global__ __launch_bounds__(256) void flash_mma_kernel(
    const float* __restrict__ Qg, const float* __restrict__ Kg,
    const float* __restrict__ Vg, float* __restrict__ Og)
{
    extern __shared__ uint32_t sm[];
    // layout: Ks[2][64][FS], Vt[2][64][FS], Ps[128][FS]
    uint32_t* Ps = sm + 4 * 64 * FS;

    const int tid = threadIdx.x;
    const int lane = tid & 31;
    const int wid = tid >> 5;
    const int l4 = lane >> 2;
    const int lm = lane & 3;

    const int qt = (gridDim.x - 1) - blockIdx.x;   // heavy tiles first
    const int h  = blockIdx.y;
    const int b  = blockIdx.z;
    const int q0 = qt * 128;

    const size_t base = (size_t)b * SS * DD + (size_t)h * DK;

    const int gr0 = q0 + wid * 16 + l4;
    const int prow = wid * 16 + l4;

    const uint32_t smb = cvta_smem(sm);
    const uint32_t psb = smb + 4 * 64 * FS * 4;

    // ldmatrix lane-address offsets (bytes, relative to a 64xFS tile base)
    uint32_t kvOff[4];
#pragma unroll
    for (int t = 0; t < 4; t++)
        kvOff[t] = ((t * 16 + (lane & 7) + 8 * ((lane >> 4) & 1)) * FS
                    + 4 * ((lane >> 3) & 1)) * 4;
    const uint32_t pOff = ((wid * 16 + (lane & 15)) * FS + ((lane >> 4) << 2)) * 4;

    // Q fragments in registers
    uint32_t qf[8][4];
#pragma unroll
    for (int ks = 0; ks < 8; ks++) {
        const float* q0p = Qg + base + (size_t)gr0 * DD;
        const float* q1p = Qg + base + (size_t)(gr0 + 8) * DD;
        qf[ks][0] = f2tf32(q0p[ks * 8 + lm]);
        qf[ks][1] = f2tf32(q1p[ks * 8 + lm]);
        qf[ks][2] = f2tf32(q0p[ks * 8 + lm + 4]);
        qf[ks][3] = f2tf32(q1p[ks * 8 + lm + 4]);
    }

    float oacc[8][4];
#pragma unroll
    for (int dt = 0; dt < 8; dt++)
#pragma unroll
        for (int r = 0; r < 4; r++) oacc[dt][r] = 0.0f;
    float m0 = -1e30f, m1 = -1e30f, l0 = 0.0f, l1 = 0.0f;

    // K/V tile register prefetch buffers
    float4 kr[4];
    float vr[16];
    auto load_kv = [&](int kt) {
        const int k0 = kt * 64;
#pragma unroll
        for (int i = 0; i < 4; i++) {
            int fi = tid + 256 * i;
            int row = fi >> 4;
            int c4 = (fi & 15) * 4;
            kr[i] = *(const float4*)(Kg + base + (size_t)(k0 + row) * DD + c4);
        }
#pragma unroll
        for (int i = 0; i < 16; i++) {
            int fi = tid + 256 * i;
            int row = fi >> 6;
            int d = fi & 63;
            vr[i] = Vg[base + (size_t)(k0 + row) * DD + d];
        }
    };
    auto store_kv = [&](int buf) {
        uint32_t* Ks = sm + buf * 64 * FS;
        uint32_t* Vt = sm + (2 + buf) * 64 * FS;
#pragma unroll
        for (int i = 0; i < 4; i++) {
            int fi = tid + 256 * i;
            int row = fi >> 4;
            int c4 = (fi & 15) * 4;
            uint32_t* dst = Ks + row * FS + c4;
            dst[0] = f2tf32(kr[i].x); dst[1] = f2tf32(kr[i].y);
            dst[2] = f2tf32(kr[i].z); dst[3] = f2tf32(kr[i].w);
        }
#pragma unroll
        for (int i = 0; i < 16; i++) {
            int fi = tid + 256 * i;
            int row = fi >> 6;
            int d = fi & 63;
            Vt[d * FS + row] = f2tf32(vr[i]);
        }
    };

    load_kv(0);
    store_kv(0);
    __syncthreads();

    const int nkt = 2 * qt + 2;
    for (int kt = 0; kt < nkt; kt++) {
        const int k0 = kt * 64;
        const int buf = kt & 1;
        const uint32_t ksBuf = smb + buf * 64 * FS * 4;
        const uint32_t vtBuf = smb + (2 + buf) * 64 * FS * 4;

        // S = Q @ K^T
        float sf[8][4];
#pragma unroll
        for (int nt = 0; nt < 8; nt++)
#pragma unroll
            for (int r = 0; r < 4; r++) sf[nt][r] = 0.0f;

#pragma unroll
        for (int ks = 0; ks < 8; ks++) {
            const uint32_t kbB = ks * 32;
#pragma unroll
            for (int t = 0; t < 4; t++) {
                uint32_t bb[4];
                ldsm_x4(bb, ksBuf + kvOff[t] + kbB);
                mma_tf32(sf[2 * t],     qf[ks], bb[0], bb[1]);
                mma_tf32(sf[2 * t + 1], qf[ks], bb[2], bb[3]);
            }
        }

        if (kt + 1 < nkt) load_kv(kt + 1);   // LDG latency hides under softmax+PV

        const float scale = 0.125f;
#pragma unroll
        for (int nt = 0; nt < 8; nt++)
#pragma unroll
            for (int r = 0; r < 4; r++) sf[nt][r] *= scale;

        if (k0 + 63 > q0 + wid * 16) {
#pragma unroll
            for (int nt = 0; nt < 8; nt++) {
                int c = k0 + nt * 8 + 2 * lm;
                if (c     > gr0)     sf[nt][0] = -1e30f;
                if (c + 1 > gr0)     sf[nt][1] = -1e30f;
                if (c     > gr0 + 8) sf[nt][2] = -1e30f;
                if (c + 1 > gr0 + 8) sf[nt][3] = -1e30f;
            }
        }

        // online softmax
        float rm0 = -1e30f, rm1 = -1e30f;
#pragma unroll
        for (int nt = 0; nt < 8; nt++) {
            rm0 = fmaxf(rm0, fmaxf(sf[nt][0], sf[nt][1]));
            rm1 = fmaxf(rm1, fmaxf(sf[nt][2], sf[nt][3]));
        }
#pragma unroll
        for (int off = 1; off <= 2; off <<= 1) {
            rm0 = fmaxf(rm0, __shfl_xor_sync(0xffffffffu, rm0, off));
            rm1 = fmaxf(rm1, __shfl_xor_sync(0xffffffffu, rm1, off));
        }
        float nm0 = fmaxf(m0, rm0), nm1 = fmaxf(m1, rm1);
        float a0 = __expf(m0 - nm0), a1 = __expf(m1 - nm1);
        float rs0 = 0.0f, rs1 = 0.0f;
#pragma unroll
        for (int nt = 0; nt < 8; nt++) {
            sf[nt][0] = __expf(sf[nt][0] - nm0);
            sf[nt][1] = __expf(sf[nt][1] - nm0);
            sf[nt][2] = __expf(sf[nt][2] - nm1);
            sf[nt][3] = __expf(sf[nt][3] - nm1);
            rs0 += sf[nt][0] + sf[nt][1];
            rs1 += sf[nt][2] + sf[nt][3];
        }
#pragma unroll
        for (int off = 1; off <= 2; off <<= 1) {
            rs0 += __shfl_xor_sync(0xffffffffu, rs0, off);
            rs1 += __shfl_xor_sync(0xffffffffu, rs1, off);
        }
        l0 = l0 * a0 + rs0;  m0 = nm0;
        l1 = l1 * a1 + rs1;  m1 = nm1;
#pragma unroll
        for (int dt = 0; dt < 8; dt++) {
            oacc[dt][0] *= a0; oacc[dt][1] *= a0;
            oacc[dt][2] *= a1; oacc[dt][3] *= a1;
        }

        // P -> smem (tf32), warp-private rows
        uint32_t* Psw = Ps;
#pragma unroll
        for (int nt = 0; nt < 8; nt++) {
            int c = nt * 8 + 2 * lm;
            uint32_t p0 = f2tf32(sf[nt][0]), p1 = f2tf32(sf[nt][1]);
            uint32_t p2 = f2tf32(sf[nt][2]), p3 = f2tf32(sf[nt][3]);
            *(uint2*)&Psw[prow * FS + c]       = make_uint2(p0, p1);
            *(uint2*)&Psw[(prow + 8) * FS + c] = make_uint2(p2, p3);
        }
        __syncwarp();

        // O += P @ V
#pragma unroll
        for (int ks = 0; ks < 8; ks++) {
            const uint32_t kbB = ks * 32;
            uint32_t af[4];
            ldsm_x4(af, psb + pOff + kbB);
#pragma unroll
            for (int t = 0; t < 4; t++) {
                uint32_t bb[4];
                ldsm_x4(bb, vtBuf + kvOff[t] + kbB);
                mma_tf32(oacc[2 * t],     af, bb[0], bb[1]);
                mma_tf32(oacc[2 * t + 1], af, bb[2], bb[3]);
            }
        }

        if (kt + 1 < nkt) {
            store_kv(buf ^ 1);
            __syncthreads();   // single sync per tile
        }
    }

    float inv0 = 1.0f / l0, inv1 = 1.0f / l1;
#pragma unroll
    for (int dt = 0; dt < 8; dt++) {
        int d = dt * 8 + 2 * lm;
        float2 o0 = make_float2(oacc[dt][0] * inv0, oacc[dt][1] * inv0);
        float2 o1 = make_float2(oacc[dt][2] * inv1, oacc[dt][3] * inv1);
        *(float2*)(Og + base + (size_t)gr0 * DD + d) = o0;
        *(float2*)(Og + base + (size_t)(gr0 + 8) * DD + d) = o1;
    }
}

// ---------------------------------------------------------------------------
// Launch
// ---------------------------------------------------------------------------
extern "C" void kernel_launch(void* const* d_in, const int* in_sizes, int n_in,
                              void* d_out, int out_size)
{
    const float* query = (const float*)d_in[0];
    const float* key   = (const float*)d_in[1];
    const float* value = (const float*)d_in[2];
    const float* wq = (const float*)d_in[3];
    const float* bq = (const float*)d_in[4];
    const float* wk = (const float*)d_in[5];
    const float* bk = (const float*)d_in[6];
    const float* wv = (const float*)d_in[7];
    const float* bv = (const float*)d_in[8];
    const float* wo = (const float*)d_in[9];
    const float* bo = (const float*)d_in[10];
    float* out = (float*)d_out;

    float *q_s, *k_s, *v_s, *o_s;
    cudaGetSymbolAddress((void**)&q_s, g_q);
    cudaGetSymbolAddress((void**)&k_s, g_k);
    cudaGetSymbolAddress((void**)&v_s, g_v);
    cudaGetSymbolAddress((void**)&o_s, g_o);

    const int smem_attn = (4 * 64 + 128) * FS * sizeof(uint32_t);  // 104448 B
    cudaFuncSetAttribute(flash_mma_kernel,
                         cudaFuncAttributeMaxDynamicSharedMemorySize, smem_attn);

    dim3 gproj3(DD / 128, MROWS / 128, 3);  // fused q/k/v projections
    gemm3_mma_kernel<<<gproj3, 128>>>(query, key, value, wq, wk, wv,
                                      bq, bk, bv, q_s, k_s, v_s);

    dim3 gattn(SS / 128, HH, BB);  // (16, 16, 2)
    flash_mma_kernel<<<gattn, 256, smem_attn>>>(q_s, k_s, v_s, o_s);

    dim3 gproj1(DD / 128, MROWS / 128, 1);  // output projection
    gemm3_mma_kernel<<<gproj1, 128>>>(o_s, o_s, o_s, wo, wo, wo,
                                      bo, bo, bo, out, out, out);
}